// round 15
// baseline (speedup 1.0000x reference)
#include <cuda_runtime.h>
#include <cuda_bf16.h>

#define N_BATCH 4096
#define T_SEQ   200

typedef __nv_bfloat16  bf16;
typedef __nv_bfloat162 bf162;

// ================= device globals (split bf16) =================
__device__ __align__(16) bf16 g_phi[4096 * 128], g_plo[4096 * 128];   // pooled split
__device__ __align__(16) bf16 g_w1h[512 * 128],  g_w1l[512 * 128];
__device__ __align__(16) bf16 g_w2h[256 * 512],  g_w2l[256 * 512];
__device__ __align__(16) bf16 g_w3h[128 * 256],  g_w3l[128 * 256];
__device__ __align__(16) bf16 g_a1h[4096 * 512], g_a1l[4096 * 512];
__device__ __align__(16) bf16 g_a2h[4096 * 256], g_a2l[4096 * 256];

// smem per buffer (bytes): AHI 0 (64x80), ALO 5120, BHI 10240 (128x80), BLO 20480.
// Row stride 80 B (32 bf16 data + 8 pad) -> conflict-free ldmatrix, 16B-mult.
// THREE buffers for a depth-2 prefetch pipeline.
#define BUFSZ      30720
#define SMEM_BYTES 92160

// ================= helpers =================
__device__ __forceinline__ unsigned smem_u32(const void* p) {
    unsigned a;
    asm("{ .reg .u64 t; cvta.to.shared.u64 t, %1; cvt.u32.u64 %0, t; }" : "=r"(a) : "l"(p));
    return a;
}
__device__ __forceinline__ void cp16(unsigned dst, const void* src) {
    asm volatile("cp.async.ca.shared.global [%0], [%1], 16;\n" :: "r"(dst), "l"(src));
}
__device__ __forceinline__ void cp_commit() { asm volatile("cp.async.commit_group;\n"); }

__device__ __forceinline__ void ldsm4(unsigned r[4], unsigned addr) {
    asm volatile("ldmatrix.sync.aligned.m8n8.x4.shared.b16 {%0,%1,%2,%3}, [%4];"
                 : "=r"(r[0]), "=r"(r[1]), "=r"(r[2]), "=r"(r[3]) : "r"(addr));
}
__device__ __forceinline__ void mma16816(float c[4], const unsigned a[4], const unsigned b[2]) {
    asm volatile("mma.sync.aligned.m16n8k16.row.col.f32.bf16.bf16.f32 "
                 "{%0,%1,%2,%3}, {%4,%5,%6,%7}, {%8,%9}, {%0,%1,%2,%3};"
                 : "+f"(c[0]), "+f"(c[1]), "+f"(c[2]), "+f"(c[3])
                 : "r"(a[0]), "r"(a[1]), "r"(a[2]), "r"(a[3]), "r"(b[0]), "r"(b[1]));
}
__device__ __forceinline__ void split2(float v, bf16& h, bf16& l) {
    h = __float2bfloat16(v);
    l = __float2bfloat16(v - __bfloat162float(h));
}

// ================= staging: one 64x32 A chunk + 128x32 B chunk (hi,lo) =================
template<int K>
__device__ __forceinline__ void stage_chunk(unsigned sb, int buf,
        const bf16* Ah, const bf16* Al, const bf16* Bh, const bf16* Bl,
        int m0, int n0, int kc, int tid) {
    unsigned dst0 = sb + (unsigned)buf * BUFSZ;
    // A: 64 rows
    {
        int r = tid >> 2, ch = tid & 3;             // r<64, ch<4
        unsigned doff = (unsigned)(r * 80 + ch * 16);
        long aoff = (long)(m0 + r) * K + kc * 32 + ch * 8;
        cp16(dst0 +        doff, Ah + aoff);
        cp16(dst0 + 5120 + doff, Al + aoff);
    }
    // B: 128 rows, two passes
    #pragma unroll
    for (int i = 0; i < 2; ++i) {
        int idx = tid + 256 * i;
        int r = idx >> 2, ch = idx & 3;             // r<128, ch<4
        unsigned doff = (unsigned)(r * 80 + ch * 16);
        long boff = (long)(n0 + r) * K + kc * 32 + ch * 8;
        cp16(dst0 + 10240 + doff, Bh + boff);
        cp16(dst0 + 20480 + doff, Bl + boff);
    }
    cp_commit();
}

// ================= GEMM mainloop: C[64,128] += split(A) @ split(B)^T =================
// 256 thr = 8 warps: wm = wid>>2 (2), wn = wid&3 (4); warp tile 32x32.
// Triple-buffered, prefetch distance 2, ONE barrier per chunk.
template<int K>
__device__ __forceinline__ void gemm_main(unsigned sb,
        const bf16* Ah, const bf16* Al, const bf16* Bh, const bf16* Bl,
        int m0, int n0, float c[2][4][4], int tid) {
    constexpr int KC = K / 32;
    int wid = tid >> 5, lane = tid & 31;
    int wm = wid >> 2, wn = wid & 3;

    stage_chunk<K>(sb, 0, Ah, Al, Bh, Bl, m0, n0, 0, tid);
    if (KC > 1) stage_chunk<K>(sb, 1, Ah, Al, Bh, Bl, m0, n0, 1, tid);

    for (int kc = 0; kc < KC; ++kc) {
        if (kc + 1 < KC) asm volatile("cp.async.wait_group 1;\n");
        else             asm volatile("cp.async.wait_group 0;\n");
        __syncthreads();
        // buffer (kc+2)%3 was last READ in iteration kc-1; the barrier above
        // ordered those reads, so restaging it now is WAR-safe.
        if (kc + 2 < KC)
            stage_chunk<K>(sb, (kc + 2) % 3, Ah, Al, Bh, Bl, m0, n0, kc + 2, tid);

        unsigned base = sb + (unsigned)(kc % 3) * BUFSZ;
        #pragma unroll
        for (int ks = 0; ks < 2; ++ks) {
            unsigned a_h[2][4], a_l[2][4];
            #pragma unroll
            for (int mi = 0; mi < 2; ++mi) {
                unsigned arow = (unsigned)(wm * 32 + mi * 16 + (lane & 15));
                unsigned aaddr = base + arow * 80 + ks * 32 + ((lane >> 4) << 4);
                ldsm4(a_h[mi], aaddr);
                ldsm4(a_l[mi], aaddr + 5120);
            }
            unsigned b_h[4][2], b_l[4][2];
            #pragma unroll
            for (int nj = 0; nj < 2; ++nj) {
                unsigned brow = (unsigned)(wn * 32 + nj * 16 + (lane & 7) + ((lane & 16) >> 1));
                unsigned baddr = base + 10240 + brow * 80 + ks * 32 + (((lane >> 3) & 1) << 4);
                unsigned t[4];
                ldsm4(t, baddr);
                b_h[nj * 2][0] = t[0]; b_h[nj * 2][1] = t[1];
                b_h[nj * 2 + 1][0] = t[2]; b_h[nj * 2 + 1][1] = t[3];
                ldsm4(t, baddr + 10240);
                b_l[nj * 2][0] = t[0]; b_l[nj * 2][1] = t[1];
                b_l[nj * 2 + 1][0] = t[2]; b_l[nj * 2 + 1][1] = t[3];
            }
            #pragma unroll
            for (int mi = 0; mi < 2; ++mi)
                #pragma unroll
                for (int ni = 0; ni < 4; ++ni) {
                    mma16816(c[mi][ni], a_h[mi], b_h[ni]);   // hi*hi
                    mma16816(c[mi][ni], a_h[mi], b_l[ni]);   // hi*lo
                    mma16816(c[mi][ni], a_l[mi], b_h[ni]);   // lo*hi
                }
        }
    }
    __syncthreads();
}

// ================= epilogue: bias+relu, split, store to global =================
template<int N>
__device__ __forceinline__ void epi_store(float c[2][4][4], const float* bias,
        bf16* Oh, bf16* Ol, int m0, int n0, int tid) {
    int wid = tid >> 5, lane = tid & 31;
    int wm = wid >> 2, wn = wid & 3;
    int g = lane >> 2, tig = lane & 3;
    #pragma unroll
    for (int mi = 0; mi < 2; ++mi)
        #pragma unroll
        for (int ni = 0; ni < 4; ++ni) {
            int col = n0 + wn * 32 + ni * 8 + 2 * tig;
            float b0v = bias[col], b1v = bias[col + 1];
            #pragma unroll
            for (int h = 0; h < 2; ++h) {
                int row = m0 + wm * 32 + mi * 16 + g + h * 8;
                float v0 = fmaxf(c[mi][ni][h * 2 + 0] + b0v, 0.f);
                float v1 = fmaxf(c[mi][ni][h * 2 + 1] + b1v, 0.f);
                bf162 hh, ll;
                split2(v0, hh.x, ll.x);
                split2(v1, hh.y, ll.y);
                *reinterpret_cast<bf162*>(Oh + (long)row * N + col) = hh;
                *reinterpret_cast<bf162*>(Ol + (long)row * N + col) = ll;
            }
        }
}

// ================= 0) prep: pooling (split out) + weight split =================
__global__ void prep_kernel(const int* __restrict__ x,
                            const int* __restrict__ lengths,
                            const float* __restrict__ emb,
                            const float* __restrict__ W1,
                            const float* __restrict__ W2,
                            const float* __restrict__ W3) {
    if (blockIdx.x < 512) {
        int gwarp = (blockIdx.x * 256 + threadIdx.x) >> 5;
        int lane  = threadIdx.x & 31;
        const int* xr = x + gwarp * T_SEQ;
        int len = lengths[gwarp];
        const float4* emb4 = (const float4*)emb;
        float4 acc = make_float4(0.f, 0.f, 0.f, 0.f);
        int t = 0;
        for (; t + 8 <= len; t += 8) {
            int4 ia = *(const int4*)(xr + t);
            int4 ib = *(const int4*)(xr + t + 4);
            float4 v0 = emb4[ia.x * 32 + lane];
            float4 v1 = emb4[ia.y * 32 + lane];
            float4 v2 = emb4[ia.z * 32 + lane];
            float4 v3 = emb4[ia.w * 32 + lane];
            float4 v4 = emb4[ib.x * 32 + lane];
            float4 v5 = emb4[ib.y * 32 + lane];
            float4 v6 = emb4[ib.z * 32 + lane];
            float4 v7 = emb4[ib.w * 32 + lane];
            acc.x += ((v0.x + v1.x) + (v2.x + v3.x)) + ((v4.x + v5.x) + (v6.x + v7.x));
            acc.y += ((v0.y + v1.y) + (v2.y + v3.y)) + ((v4.y + v5.y) + (v6.y + v7.y));
            acc.z += ((v0.z + v1.z) + (v2.z + v3.z)) + ((v4.z + v5.z) + (v6.z + v7.z));
            acc.w += ((v0.w + v1.w) + (v2.w + v3.w)) + ((v4.w + v5.w) + (v6.w + v7.w));
        }
        for (; t < len; ++t) {
            float4 a = emb4[xr[t] * 32 + lane];
            acc.x += a.x; acc.y += a.y; acc.z += a.z; acc.w += a.w;
        }
        float inv = 1.0f / (float)len;
        float vv[4] = {acc.x * inv, acc.y * inv, acc.z * inv, acc.w * inv};
        bf162 h01, l01, h23, l23;
        split2(vv[0], h01.x, l01.x); split2(vv[1], h01.y, l01.y);
        split2(vv[2], h23.x, l23.x); split2(vv[3], h23.y, l23.y);
        long base = (long)gwarp * 128 + 4 * lane;
        *reinterpret_cast<bf162*>(g_phi + base)     = h01;
        *reinterpret_cast<bf162*>(g_phi + base + 2) = h23;
        *reinterpret_cast<bf162*>(g_plo + base)     = l01;
        *reinterpret_cast<bf162*>(g_plo + base + 2) = l23;
    } else {
        int idx = (blockIdx.x - 512) * 256 + threadIdx.x;
        if (idx < 65536) {
            bf16 h, l; split2(W1[idx], h, l);
            g_w1h[idx] = h; g_w1l[idx] = l;
        } else if (idx < 65536 + 131072) {
            int i2 = idx - 65536;
            bf16 h, l; split2(W2[i2], h, l);
            g_w2h[i2] = h; g_w2l[i2] = l;
        } else if (idx < 65536 + 131072 + 32768) {
            int i3 = idx - 65536 - 131072;
            bf16 h, l; split2(W3[i3], h, l);
            g_w3h[i3] = h; g_w3l[i3] = l;
        }
    }
}

// ================= layer kernels =================
__global__ void __launch_bounds__(256) l1_kernel(const float* __restrict__ b1) {
    extern __shared__ __align__(16) unsigned char smem[];
    unsigned sb = smem_u32(smem);
    int tid = threadIdx.x;
    int m0 = blockIdx.x * 64, n0 = blockIdx.y * 128;
    float c[2][4][4];
    #pragma unroll
    for (int i = 0; i < 2; ++i)
        #pragma unroll
        for (int j = 0; j < 4; ++j)
            #pragma unroll
            for (int q = 0; q < 4; ++q) c[i][j][q] = 0.f;
    gemm_main<128>(sb, g_phi, g_plo, g_w1h, g_w1l, m0, n0, c, tid);
    epi_store<512>(c, b1, g_a1h, g_a1l, m0, n0, tid);
}

__global__ void __launch_bounds__(256) l2_kernel(const float* __restrict__ b2) {
    extern __shared__ __align__(16) unsigned char smem[];
    unsigned sb = smem_u32(smem);
    int tid = threadIdx.x;
    int m0 = blockIdx.x * 64, n0 = blockIdx.y * 128;
    float c[2][4][4];
    #pragma unroll
    for (int i = 0; i < 2; ++i)
        #pragma unroll
        for (int j = 0; j < 4; ++j)
            #pragma unroll
            for (int q = 0; q < 4; ++q) c[i][j][q] = 0.f;
    gemm_main<512>(sb, g_a1h, g_a1l, g_w2h, g_w2l, m0, n0, c, tid);
    epi_store<256>(c, b2, g_a2h, g_a2l, m0, n0, tid);
}

__global__ void __launch_bounds__(256) l3_kernel(const float* __restrict__ b3,
                                                 const float* __restrict__ W4,
                                                 const float* __restrict__ b4,
                                                 float* __restrict__ out) {
    extern __shared__ __align__(16) unsigned char smem[];
    unsigned sb = smem_u32(smem);
    int tid = threadIdx.x;
    int m0 = blockIdx.x * 64;
    float c[2][4][4];
    #pragma unroll
    for (int i = 0; i < 2; ++i)
        #pragma unroll
        for (int j = 0; j < 4; ++j)
            #pragma unroll
            for (int q = 0; q < 4; ++q) c[i][j][q] = 0.f;
    gemm_main<256>(sb, g_a2h, g_a2l, g_w3h, g_w3l, m0, 0, c, tid);

    // h3 (relu'd fp32) -> smem [64][130]
    float* h3 = (float*)smem;
    {
        int wid = tid >> 5, lane = tid & 31;
        int wm = wid >> 2, wn = wid & 3;
        int g = lane >> 2, tig = lane & 3;
        #pragma unroll
        for (int mi = 0; mi < 2; ++mi)
            #pragma unroll
            for (int ni = 0; ni < 4; ++ni) {
                int col = wn * 32 + ni * 8 + 2 * tig;
                float b0v = b3[col], b1v = b3[col + 1];
                #pragma unroll
                for (int h = 0; h < 2; ++h) {
                    int row = wm * 32 + mi * 16 + g + h * 8;
                    h3[row * 130 + col]     = fmaxf(c[mi][ni][h * 2 + 0] + b0v, 0.f);
                    h3[row * 130 + col + 1] = fmaxf(c[mi][ni][h * 2 + 1] + b1v, 0.f);
                }
            }
    }
    __syncthreads();

    // fused layer 4 (64 rows x 2 outputs = 128 threads)
    if (tid < 128) {
        int r = tid >> 1, jo = tid & 1;
        float acc = b4[jo];
        #pragma unroll 8
        for (int k = 0; k < 128; ++k)
            acc += h3[r * 130 + k] * W4[jo * 128 + k];
        out[(m0 + r) * 2 + jo] = acc;
    }
}

// ================= launch =================
extern "C" void kernel_launch(void* const* d_in, const int* in_sizes, int n_in,
                              void* d_out, int out_size) {
    const int*   x       = (const int*)  d_in[0];
    const int*   lengths = (const int*)  d_in[1];
    const float* emb     = (const float*)d_in[2];
    const float* W1      = (const float*)d_in[3];
    const float* b1      = (const float*)d_in[4];
    const float* W2      = (const float*)d_in[5];
    const float* b2      = (const float*)d_in[6];
    const float* W3      = (const float*)d_in[7];
    const float* b3      = (const float*)d_in[8];
    const float* W4      = (const float*)d_in[9];
    const float* b4      = (const float*)d_in[10];
    float* out = (float*)d_out;

    cudaFuncSetAttribute(l1_kernel, cudaFuncAttributeMaxDynamicSharedMemorySize, SMEM_BYTES);
    cudaFuncSetAttribute(l2_kernel, cudaFuncAttributeMaxDynamicSharedMemorySize, SMEM_BYTES);
    cudaFuncSetAttribute(l3_kernel, cudaFuncAttributeMaxDynamicSharedMemorySize, SMEM_BYTES);

    prep_kernel<<<1408, 256>>>(x, lengths, emb, W1, W2, W3);
    l1_kernel<<<dim3(64, 4), 256, SMEM_BYTES>>>(b1);
    l2_kernel<<<dim3(64, 2), 256, SMEM_BYTES>>>(b2);
    l3_kernel<<<dim3(64, 1), 256, SMEM_BYTES>>>(b3, W4, b4, out);
}

// round 16
// speedup vs baseline: 1.0352x; 1.0352x over previous
#include <cuda_runtime.h>
#include <cuda_bf16.h>

#define N_BATCH 4096
#define T_SEQ   200

typedef __nv_bfloat16  bf16;
typedef __nv_bfloat162 bf162;

// ================= device globals (split bf16) =================
__device__ __align__(16) bf16 g_phi[4096 * 128], g_plo[4096 * 128];
__device__ __align__(16) bf16 g_w1h[512 * 128],  g_w1l[512 * 128];
__device__ __align__(16) bf16 g_w2h[256 * 512],  g_w2l[256 * 512];
__device__ __align__(16) bf16 g_w3h[128 * 256],  g_w3l[128 * 256];

// ================= smem map (bytes) =================
// A   (pooled, split): 32 rows x 272B (256 data + 16 pad); hi at 0, lo at +8704
#define A_OFF     0
#define A_STRIDE  272
#define A_LO      8704
// h1 (split): 32 rows x 1040B; hi at H1_OFF, lo at +33280
#define H1_OFF    17408
#define H1_STRIDE 1040
#define H1_LO     33280
// h2 (split): 32 rows x 528B; hi at H2_OFF, lo at +16896
#define H2_OFF    83968
#define H2_STRIDE 528
#define H2_LO     16896
// B staging: 2 buffers x (128 rows x 80B hi + same lo) = 2 x 20480
#define BST_OFF   117760
#define BBUF      20480
// h3 fp32 overlay on B staging (L3 epilogue, staging drained)
#define H3_OFF    117760
#define SMEM_BYTES 158720

// ================= helpers =================
__device__ __forceinline__ unsigned smem_u32(const void* p) {
    unsigned a;
    asm("{ .reg .u64 t; cvta.to.shared.u64 t, %1; cvt.u32.u64 %0, t; }" : "=r"(a) : "l"(p));
    return a;
}
__device__ __forceinline__ void cp16(unsigned dst, const void* src) {
    asm volatile("cp.async.ca.shared.global [%0], [%1], 16;\n" :: "r"(dst), "l"(src));
}
__device__ __forceinline__ void cp_commit() { asm volatile("cp.async.commit_group;\n"); }

__device__ __forceinline__ void ldsm4(unsigned r[4], unsigned addr) {
    asm volatile("ldmatrix.sync.aligned.m8n8.x4.shared.b16 {%0,%1,%2,%3}, [%4];"
                 : "=r"(r[0]), "=r"(r[1]), "=r"(r[2]), "=r"(r[3]) : "r"(addr));
}
__device__ __forceinline__ void mma16816(float c[4], const unsigned a[4], const unsigned b[2]) {
    asm volatile("mma.sync.aligned.m16n8k16.row.col.f32.bf16.bf16.f32 "
                 "{%0,%1,%2,%3}, {%4,%5,%6,%7}, {%8,%9}, {%0,%1,%2,%3};"
                 : "+f"(c[0]), "+f"(c[1]), "+f"(c[2]), "+f"(c[3])
                 : "r"(a[0]), "r"(a[1]), "r"(a[2]), "r"(a[3]), "r"(b[0]), "r"(b[1]));
}
__device__ __forceinline__ void split2(float v, bf16& h, bf16& l) {
    h = __float2bfloat16(v);
    l = __float2bfloat16(v - __bfloat162float(h));
}

// ================= 0) prep: pooling (split out) + weight split =================
__global__ void prep_kernel(const int* __restrict__ x,
                            const int* __restrict__ lengths,
                            const float* __restrict__ emb,
                            const float* __restrict__ W1,
                            const float* __restrict__ W2,
                            const float* __restrict__ W3) {
    if (blockIdx.x < 512) {
        int gwarp = (blockIdx.x * 256 + threadIdx.x) >> 5;
        int lane  = threadIdx.x & 31;
        const int* xr = x + gwarp * T_SEQ;
        int len = lengths[gwarp];
        const float4* emb4 = (const float4*)emb;
        float4 acc = make_float4(0.f, 0.f, 0.f, 0.f);
        int t = 0;
        for (; t + 8 <= len; t += 8) {
            int4 ia = *(const int4*)(xr + t);
            int4 ib = *(const int4*)(xr + t + 4);
            float4 v0 = emb4[ia.x * 32 + lane];
            float4 v1 = emb4[ia.y * 32 + lane];
            float4 v2 = emb4[ia.z * 32 + lane];
            float4 v3 = emb4[ia.w * 32 + lane];
            float4 v4 = emb4[ib.x * 32 + lane];
            float4 v5 = emb4[ib.y * 32 + lane];
            float4 v6 = emb4[ib.z * 32 + lane];
            float4 v7 = emb4[ib.w * 32 + lane];
            acc.x += ((v0.x + v1.x) + (v2.x + v3.x)) + ((v4.x + v5.x) + (v6.x + v7.x));
            acc.y += ((v0.y + v1.y) + (v2.y + v3.y)) + ((v4.y + v5.y) + (v6.y + v7.y));
            acc.z += ((v0.z + v1.z) + (v2.z + v3.z)) + ((v4.z + v5.z) + (v6.z + v7.z));
            acc.w += ((v0.w + v1.w) + (v2.w + v3.w)) + ((v4.w + v5.w) + (v6.w + v7.w));
        }
        for (; t < len; ++t) {
            float4 a = emb4[xr[t] * 32 + lane];
            acc.x += a.x; acc.y += a.y; acc.z += a.z; acc.w += a.w;
        }
        float inv = 1.0f / (float)len;
        float vv[4] = {acc.x * inv, acc.y * inv, acc.z * inv, acc.w * inv};
        bf162 h01, l01, h23, l23;
        split2(vv[0], h01.x, l01.x); split2(vv[1], h01.y, l01.y);
        split2(vv[2], h23.x, l23.x); split2(vv[3], h23.y, l23.y);
        long base = (long)gwarp * 128 + 4 * lane;
        *reinterpret_cast<bf162*>(g_phi + base)     = h01;
        *reinterpret_cast<bf162*>(g_phi + base + 2) = h23;
        *reinterpret_cast<bf162*>(g_plo + base)     = l01;
        *reinterpret_cast<bf162*>(g_plo + base + 2) = l23;
    } else {
        int idx = (blockIdx.x - 512) * 256 + threadIdx.x;
        if (idx < 65536) {
            bf16 h, l; split2(W1[idx], h, l);
            g_w1h[idx] = h; g_w1l[idx] = l;
        } else if (idx < 65536 + 131072) {
            int i2 = idx - 65536;
            bf16 h, l; split2(W2[i2], h, l);
            g_w2h[i2] = h; g_w2l[i2] = l;
        } else if (idx < 65536 + 131072 + 32768) {
            int i3 = idx - 65536 - 131072;
            bf16 h, l; split2(W3[i3], h, l);
            g_w3h[i3] = h; g_w3l[i3] = l;
        }
    }
}

// ================= fused MLP kernel: 32 rows per block =================
// 256 thr = 8 warps, warp tile 32x16 (mi 2 x ni 2 fragments).
// B chunk staging: 128 rows x 32 k (hi+lo), double-buffered.
template<int K>
__device__ __forceinline__ void stage_b(unsigned sb, int buf,
        const bf16* Bh, const bf16* Bl, int n0, int kc, int tid) {
    unsigned dst0 = sb + BST_OFF + (unsigned)buf * BBUF;
    #pragma unroll
    for (int i = 0; i < 2; ++i) {
        int idx = tid + 256 * i;
        int r = idx >> 2, ch = idx & 3;
        unsigned doff = (unsigned)(r * 80 + ch * 16);
        long boff = (long)(n0 + r) * K + kc * 32 + ch * 8;
        cp16(dst0 +         doff, Bh + boff);
        cp16(dst0 + 10240 + doff, Bl + boff);
    }
    cp_commit();
}

// compute one 32-k chunk: A at (abase,astride,alo), chunk col = kc*64 bytes
__device__ __forceinline__ void chunk_mma(unsigned sb, unsigned abase, int astride,
        unsigned alo, int kc, int buf, unsigned b_row_off, float c[2][2][4], int lane) {
    unsigned bbase = sb + BST_OFF + (unsigned)buf * BBUF + b_row_off;
    #pragma unroll
    for (int ks = 0; ks < 2; ++ks) {
        unsigned a_h[2][4], a_l[2][4];
        #pragma unroll
        for (int mi = 0; mi < 2; ++mi) {
            unsigned aaddr = abase + (unsigned)((mi * 16 + (lane & 15)) * astride)
                           + (unsigned)(kc * 64 + ks * 32) + ((lane >> 4) << 4);
            ldsm4(a_h[mi], aaddr);
            ldsm4(a_l[mi], aaddr + alo);
        }
        unsigned t[4];
        unsigned b_h[2][2], b_l[2][2];
        ldsm4(t, bbase + ks * 32);
        b_h[0][0] = t[0]; b_h[0][1] = t[1]; b_h[1][0] = t[2]; b_h[1][1] = t[3];
        ldsm4(t, bbase + 10240 + ks * 32);
        b_l[0][0] = t[0]; b_l[0][1] = t[1]; b_l[1][0] = t[2]; b_l[1][1] = t[3];
        #pragma unroll
        for (int mi = 0; mi < 2; ++mi)
            #pragma unroll
            for (int ni = 0; ni < 2; ++ni) {
                mma16816(c[mi][ni], a_h[mi], b_h[ni]);
                mma16816(c[mi][ni], a_h[mi], b_l[ni]);
                mma16816(c[mi][ni], a_l[mi], b_h[ni]);
            }
    }
}

__global__ void __launch_bounds__(256) mlp_kernel(
        const float* __restrict__ b1, const float* __restrict__ b2,
        const float* __restrict__ b3, const float* __restrict__ W4,
        const float* __restrict__ b4, float* __restrict__ out) {
    extern __shared__ __align__(16) unsigned char smem[];
    unsigned sb = smem_u32(smem);
    int tid = threadIdx.x, wid = tid >> 5, lane = tid & 31;
    int m0 = blockIdx.x * 32;

    unsigned b_row_off = (unsigned)((wid * 16 + (lane & 7) + ((lane & 16) >> 1)) * 80
                       + (((lane >> 3) & 1) << 4));
    int g = lane >> 2, tig = lane & 3;

    // ---- stage pooled A (hi/lo) + first B chunk of layer 1, one cp group ----
    #pragma unroll
    for (int i = 0; i < 2; ++i) {
        int idx = tid + 256 * i;
        int r = idx >> 4, ch = idx & 15;
        unsigned doff = (unsigned)(A_OFF + r * A_STRIDE + ch * 16);
        long soff = (long)(m0 + r) * 128 + ch * 8;
        cp16(sb + doff,        g_phi + soff);
        cp16(sb + doff + A_LO, g_plo + soff);
    }
    stage_b<128>(sb, 0, g_w1h, g_w1l, 0, 0, tid);   // commits group

    float c[2][2][4];
    #pragma unroll
    for (int i = 0; i < 2; ++i)
        #pragma unroll
        for (int j = 0; j < 2; ++j)
            #pragma unroll
            for (int q = 0; q < 4; ++q) c[i][j][q] = 0.f;

    // =========== layer 1: K=128 (KC=4), N=512 (NC=4) ===========
    {
        const int KC = 4, NC = 4, T = KC * NC;
        for (int it = 0; it < T; ++it) {
            int nc = it / KC, kc = it % KC;
            if (it + 1 < T) {
                int nn = (it + 1) / KC, nk = (it + 1) % KC;
                stage_b<128>(sb, (it + 1) & 1, g_w1h, g_w1l, nn * 128, nk, tid);
                asm volatile("cp.async.wait_group 1;\n");
            } else asm volatile("cp.async.wait_group 0;\n");
            __syncthreads();
            chunk_mma(sb, sb + A_OFF, A_STRIDE, A_LO, kc, it & 1, b_row_off, c, lane);
            if (kc == KC - 1) {   // epilogue for this N-chunk
                #pragma unroll
                for (int mi = 0; mi < 2; ++mi)
                    #pragma unroll
                    for (int ni = 0; ni < 2; ++ni) {
                        int col = nc * 128 + wid * 16 + ni * 8 + 2 * tig;
                        float b0v = b1[col], b1v = b1[col + 1];
                        #pragma unroll
                        for (int h = 0; h < 2; ++h) {
                            int row = mi * 16 + g + h * 8;
                            float v0 = fmaxf(c[mi][ni][h * 2 + 0] + b0v, 0.f);
                            float v1 = fmaxf(c[mi][ni][h * 2 + 1] + b1v, 0.f);
                            bf162 hh, ll;
                            split2(v0, hh.x, ll.x);
                            split2(v1, hh.y, ll.y);
                            unsigned off = (unsigned)(H1_OFF + row * H1_STRIDE + col * 2);
                            *reinterpret_cast<bf162*>(smem + off)         = hh;
                            *reinterpret_cast<bf162*>(smem + off + H1_LO) = ll;
                            c[mi][ni][h * 2] = 0.f; c[mi][ni][h * 2 + 1] = 0.f;
                        }
                    }
            }
        }
    }
    __syncthreads();
    // prefetch layer-2 chunk 0
    stage_b<512>(sb, 0, g_w2h, g_w2l, 0, 0, tid);

    // =========== layer 2: K=512 (KC=16), N=256 (NC=2) ===========
    {
        const int KC = 16, NC = 2, T = KC * NC;
        for (int it = 0; it < T; ++it) {
            int nc = it / KC, kc = it % KC;
            if (it + 1 < T) {
                int nn = (it + 1) / KC, nk = (it + 1) % KC;
                stage_b<512>(sb, (it + 1) & 1, g_w2h, g_w2l, nn * 128, nk, tid);
                asm volatile("cp.async.wait_group 1;\n");
            } else asm volatile("cp.async.wait_group 0;\n");
            __syncthreads();
            chunk_mma(sb, sb + H1_OFF, H1_STRIDE, H1_LO, kc, it & 1, b_row_off, c, lane);
            if (kc == KC - 1) {
                #pragma unroll
                for (int mi = 0; mi < 2; ++mi)
                    #pragma unroll
                    for (int ni = 0; ni < 2; ++ni) {
                        int col = nc * 128 + wid * 16 + ni * 8 + 2 * tig;
                        float b0v = b2[col], b1v = b2[col + 1];
                        #pragma unroll
                        for (int h = 0; h < 2; ++h) {
                            int row = mi * 16 + g + h * 8;
                            float v0 = fmaxf(c[mi][ni][h * 2 + 0] + b0v, 0.f);
                            float v1 = fmaxf(c[mi][ni][h * 2 + 1] + b1v, 0.f);
                            bf162 hh, ll;
                            split2(v0, hh.x, ll.x);
                            split2(v1, hh.y, ll.y);
                            unsigned off = (unsigned)(H2_OFF + row * H2_STRIDE + col * 2);
                            *reinterpret_cast<bf162*>(smem + off)         = hh;
                            *reinterpret_cast<bf162*>(smem + off + H2_LO) = ll;
                            c[mi][ni][h * 2] = 0.f; c[mi][ni][h * 2 + 1] = 0.f;
                        }
                    }
            }
        }
    }
    __syncthreads();
    stage_b<256>(sb, 0, g_w3h, g_w3l, 0, 0, tid);

    // =========== layer 3: K=256 (KC=8), N=128 ===========
    {
        const int KC = 8;
        for (int kc = 0; kc < KC; ++kc) {
            if (kc + 1 < KC) {
                stage_b<256>(sb, (kc + 1) & 1, g_w3h, g_w3l, 0, kc + 1, tid);
                asm volatile("cp.async.wait_group 1;\n");
            } else asm volatile("cp.async.wait_group 0;\n");
            __syncthreads();
            chunk_mma(sb, sb + H2_OFF, H2_STRIDE, H2_LO, kc, kc & 1, b_row_off, c, lane);
        }
    }
    __syncthreads();   // B staging fully drained -> h3 overlay safe

    // h3 epilogue: fp32 relu to smem [32][130]
    {
        float* h3 = (float*)(smem + H3_OFF);
        #pragma unroll
        for (int mi = 0; mi < 2; ++mi)
            #pragma unroll
            for (int ni = 0; ni < 2; ++ni) {
                int col = wid * 16 + ni * 8 + 2 * tig;
                float b0v = b3[col], b1v = b3[col + 1];
                #pragma unroll
                for (int h = 0; h < 2; ++h) {
                    int row = mi * 16 + g + h * 8;
                    h3[row * 130 + col]     = fmaxf(c[mi][ni][h * 2 + 0] + b0v, 0.f);
                    h3[row * 130 + col + 1] = fmaxf(c[mi][ni][h * 2 + 1] + b1v, 0.f);
                }
            }
    }
    __syncthreads();

    // fused layer 4: 32 rows x 2 outputs
    if (tid < 64) {
        const float* h3 = (const float*)(smem + H3_OFF);
        int r = tid >> 1, jo = tid & 1;
        float acc = b4[jo];
        #pragma unroll 8
        for (int k = 0; k < 128; ++k)
            acc += h3[r * 130 + k] * W4[jo * 128 + k];
        out[(m0 + r) * 2 + jo] = acc;
    }
}

// ================= launch =================
extern "C" void kernel_launch(void* const* d_in, const int* in_sizes, int n_in,
                              void* d_out, int out_size) {
    const int*   x       = (const int*)  d_in[0];
    const int*   lengths = (const int*)  d_in[1];
    const float* emb     = (const float*)d_in[2];
    const float* W1      = (const float*)d_in[3];
    const float* b1      = (const float*)d_in[4];
    const float* W2      = (const float*)d_in[5];
    const float* b2      = (const float*)d_in[6];
    const float* W3      = (const float*)d_in[7];
    const float* b3      = (const float*)d_in[8];
    const float* W4      = (const float*)d_in[9];
    const float* b4      = (const float*)d_in[10];
    float* out = (float*)d_out;

    cudaFuncSetAttribute(mlp_kernel, cudaFuncAttributeMaxDynamicSharedMemorySize, SMEM_BYTES);

    prep_kernel<<<1408, 256>>>(x, lengths, emb, W1, W2, W3);
    mlp_kernel<<<128, 256, SMEM_BYTES>>>(b1, b2, b3, W4, b4, out);
}